// round 1
// baseline (speedup 1.0000x reference)
#include <cuda_runtime.h>

#define B_TOTAL 2097152
#define NPHI    128
#define NSTEP   127
#define NCOEF   64      // odd Chebyshev coefficients T_1, T_3, ..., T_127
#define EPT     4       // elements per thread in eval kernel
#define TPB     256

// Precomputed complex coefficients alpha_j: u00(theta) = sum_j alpha_j * cos((2j+1) theta)
__device__ float2 g_alpha[NCOEF];

// ---------------- f32x2 packed helpers (sm_100+) ----------------
__device__ __forceinline__ unsigned long long pk2(float lo, float hi) {
    unsigned long long r;
    asm("mov.b64 %0, {%1, %2};" : "=l"(r) : "f"(lo), "f"(hi));
    return r;
}
__device__ __forceinline__ void upk2(unsigned long long v, float& lo, float& hi) {
    asm("mov.b64 {%0, %1}, %2;" : "=f"(lo), "=f"(hi) : "l"(v));
}
__device__ __forceinline__ unsigned long long fma2(unsigned long long a,
                                                   unsigned long long b,
                                                   unsigned long long c) {
    unsigned long long d;
    asm("fma.rn.f32x2 %0, %1, %2, %3;" : "=l"(d) : "l"(a), "l"(b), "l"(c));
    return d;
}
__device__ __forceinline__ unsigned long long mul2(unsigned long long a,
                                                   unsigned long long b) {
    unsigned long long d;
    asm("mul.rn.f32x2 %0, %1, %2;" : "=l"(d) : "l"(a), "l"(b));
    return d;
}
// a - b  implemented as fma(-1, b, a) to rely only on fma.rn.f32x2
__device__ __forceinline__ unsigned long long sub2(unsigned long long a,
                                                   unsigned long long b) {
    const unsigned long long NEG1 = 0xBF800000BF800000ull; // (-1.0f, -1.0f)
    return fma2(NEG1, b, a);
}

// ---------------- Kernel A: coefficient precompute (1 block) ----------------
// Frequency-domain recursion for u's top row (a, b) as trig polynomials:
//   a'_m = e_k  * ( (a_{m-1}+a_{m+1}) + (b_{m-1}-b_{m+1}) ) / 2
//   b'_m = e_k* * ( (a_{m-1}-a_{m+1}) + (b_{m-1}+b_{m+1}) ) / 2
// m in [-127,127], idx = m+127, stored at smem position idx+1 (borders = 0).
__global__ void qsp_coef_kernel(const float* __restrict__ phis) {
    __shared__ float2 e[NPHI];        // (cos phi_k, sin phi_k)
    __shared__ float4 buf0[257];      // (a_r, a_i, b_r, b_i), padded
    __shared__ float4 buf1[257];

    int t = threadIdx.x;
    if (t < NPHI) {
        float s, c;
        sincosf(phis[t], &s, &c);
        e[t] = make_float2(c, s);
    }
    for (int i = t; i < 257; i += blockDim.x) {
        buf0[i] = make_float4(0.f, 0.f, 0.f, 0.f);
        buf1[i] = make_float4(0.f, 0.f, 0.f, 0.f);
    }
    __syncthreads();
    if (t == 0) {
        // init: a = e^{i phi_0} at m=0 (idx 127 -> pos 128), b = 0
        buf0[128] = make_float4(e[0].x, e[0].y, 0.f, 0.f);
    }
    __syncthreads();

    float4* cur = buf0;
    float4* nxt = buf1;
    for (int k = 1; k <= NSTEP; k++) {
        if (t < 255) {
            float4 L = cur[t];       // idx-1
            float4 R = cur[t + 2];   // idx+1
            float s1r = 0.5f * (L.x + R.x + L.z - R.z);
            float s1i = 0.5f * (L.y + R.y + L.w - R.w);
            float s2r = 0.5f * (L.x - R.x + L.z + R.z);
            float s2i = 0.5f * (L.y - R.y + L.w + R.w);
            float er = e[k].x, ei = e[k].y;
            float4 o;
            o.x = er * s1r - ei * s1i;   // a' = e_k * s1
            o.y = er * s1i + ei * s1r;
            o.z = er * s2r + ei * s2i;   // b' = conj(e_k) * s2
            o.w = er * s2i - ei * s2r;
            nxt[t + 1] = o;
        }
        __syncthreads();
        float4* tmp = cur; cur = nxt; nxt = tmp;
    }

    if (t < NCOEF) {
        // m = 2t+1 -> pos 2t+129 ; m = -(2t+1) -> pos 127-2t
        float4 p = cur[2 * t + 129];
        float4 q = cur[127 - 2 * t];
        g_alpha[t] = make_float2(p.x + q.x, p.y + q.y);  // symmetrized cos coefficient
    }
}

// ---------------- Kernel B: per-element Clenshaw eval ----------------
// S(theta) = sum_j alpha_j cos((2j+1) theta), u = 2 cos 2theta = 4c^2 - 2:
//   b_j = alpha_j + u*b_{j+1} - b_{j+2};  S = c * (b_0 - b_1)
// (real, imag) packed into one f32x2 lane.
__global__ void __launch_bounds__(TPB) qsp_eval_kernel(const float* __restrict__ th,
                                                       float* __restrict__ out) {
    __shared__ unsigned long long sc[NCOEF];
    int t = threadIdx.x;
    if (t < NCOEF) {
        float2 a = g_alpha[t];
        sc[t] = pk2(a.x, a.y);
    }
    __syncthreads();

    int base = (blockIdx.x * TPB + t) * EPT;
    float4 th4 = *reinterpret_cast<const float4*>(th + base);

    float c[EPT];
    c[0] = cosf(th4.x);
    c[1] = cosf(th4.y);
    c[2] = cosf(th4.z);
    c[3] = cosf(th4.w);

    unsigned long long U[EPT], b1[EPT], b2[EPT];
#pragma unroll
    for (int eidx = 0; eidx < EPT; eidx++) {
        float u = fmaf(4.0f * c[eidx], c[eidx], -2.0f);  // 2*cos(2 theta)
        U[eidx]  = pk2(u, u);
        b1[eidx] = 0ull;
        b2[eidx] = 0ull;
    }

#pragma unroll
    for (int j = NCOEF - 1; j >= 0; j--) {
        unsigned long long al = sc[j];
#pragma unroll
        for (int eidx = 0; eidx < EPT; eidx++) {
            unsigned long long tm = sub2(al, b2[eidx]);           // alpha_j - b2
            unsigned long long bn = fma2(U[eidx], b1[eidx], tm);  // + u*b1
            b2[eidx] = b1[eidx];
            b1[eidx] = bn;
        }
    }

    float4 re, im;
#pragma unroll
    for (int eidx = 0; eidx < EPT; eidx++) {
        unsigned long long d = sub2(b1[eidx], b2[eidx]);          // b0 - b1
        unsigned long long S = mul2(d, pk2(c[eidx], c[eidx]));    // * cos theta
        float r, i;
        upk2(S, r, i);
        (&re.x)[eidx] = r;
        (&im.x)[eidx] = i;
    }

    *reinterpret_cast<float4*>(out + base)           = re;
    *reinterpret_cast<float4*>(out + B_TOTAL + base) = im;
}

// ---------------- Launch ----------------
extern "C" void kernel_launch(void* const* d_in, const int* in_sizes, int n_in,
                              void* d_out, int out_size) {
    const float* th   = (const float*)d_in[0];
    const float* phis = (const float*)d_in[1];
    // defensive: identify inputs by size (th has B_TOTAL elems, phis has 128)
    if (n_in >= 2 && in_sizes[0] == NPHI) {
        phis = (const float*)d_in[0];
        th   = (const float*)d_in[1];
    }
    float* out = (float*)d_out;

    qsp_coef_kernel<<<1, 256>>>(phis);

    int nthreads = B_TOTAL / EPT;           // 524288
    qsp_eval_kernel<<<nthreads / TPB, TPB>>>(th, out);
}

// round 2
// speedup vs baseline: 1.6134x; 1.6134x over previous
#include <cuda_runtime.h>

#define B_TOTAL 2097152
#define NPHI    128
#define NSTEP   127
#define NCOEF   64      // odd cos coefficients: u00 = sum_j alpha_j cos((2j+1)theta)
#define EPT     4       // elements per thread in eval kernel
#define TPB     256

// Packed (re, im) complex coefficients
__device__ unsigned long long g_alpha[NCOEF];

// ---------------- f32x2 packed helpers (sm_100+) ----------------
__device__ __forceinline__ unsigned long long pk2(float lo, float hi) {
    unsigned long long r;
    asm("mov.b64 %0, {%1, %2};" : "=l"(r) : "f"(lo), "f"(hi));
    return r;
}
__device__ __forceinline__ void upk2(unsigned long long v, float& lo, float& hi) {
    asm("mov.b64 {%0, %1}, %2;" : "=f"(lo), "=f"(hi) : "l"(v));
}
__device__ __forceinline__ unsigned long long fma2(unsigned long long a,
                                                   unsigned long long b,
                                                   unsigned long long c) {
    unsigned long long d;
    asm("fma.rn.f32x2 %0, %1, %2, %3;" : "=l"(d) : "l"(a), "l"(b), "l"(c));
    return d;
}
__device__ __forceinline__ unsigned long long mul2(unsigned long long a,
                                                   unsigned long long b) {
    unsigned long long d;
    asm("mul.rn.f32x2 %0, %1, %2;" : "=l"(d) : "l"(a), "l"(b));
    return d;
}
__device__ __forceinline__ unsigned long long add2(unsigned long long a,
                                                   unsigned long long b) {
    unsigned long long d;
    asm("add.rn.f32x2 %0, %1, %2;" : "=l"(d) : "l"(a), "l"(b));
    return d;
}
// a - b via fma(-1, b, a)
__device__ __forceinline__ unsigned long long sub2(unsigned long long a,
                                                   unsigned long long b) {
    const unsigned long long NEG1 = 0xBF800000BF800000ull;
    return fma2(NEG1, b, a);
}

// ---------------- Kernel A: coefficient precompute (1 block) ----------------
// Frequency-domain recursion for the top row (a, b) of the unitary chain.
// Positions m in [-127,127] -> idx = m+127 -> stored at smem slot idx+1
// (slots 0 and 256 are permanent zero borders).
//   a'_m = e_k  * 0.5*( (a_{m-1}+a_{m+1}) + (b_{m-1}-b_{m+1}) )
//   b'_m = e_k* * 0.5*( (a_{m-1}-a_{m+1}) + (b_{m-1}+b_{m+1}) )
// 0.5 is folded into the stored e_k.
__global__ void qsp_coef_kernel(const float* __restrict__ phis) {
    // earliest possible launch of the dependent eval kernel
    cudaTriggerProgrammaticLaunchCompletion();

    __shared__ float2 e[NPHI];                 // (0.5 cos phi_k, 0.5 sin phi_k)
    __shared__ unsigned long long A0[257], B0[257], A1[257], B1[257];

    int t = threadIdx.x;
    if (t < NPHI) {
        float s, c;
        sincosf(phis[t], &s, &c);
        e[t] = make_float2(0.5f * c, 0.5f * s);
    }
    for (int i = t; i < 257; i += blockDim.x) {
        A0[i] = 0ull; B0[i] = 0ull; A1[i] = 0ull; B1[i] = 0ull;
    }
    __syncthreads();
    if (t == 0) {
        // a = e^{i phi_0} at m=0 (idx 127 -> slot 128); undo the 0.5 fold
        A0[128] = pk2(2.0f * e[0].x, 2.0f * e[0].y);
    }
    __syncthreads();

    unsigned long long *Ac = A0, *Bc = B0, *An = A1, *Bn = B1;
    for (int k = 1; k <= NSTEP; k++) {
        if (t < 255) {
            unsigned long long La = Ac[t], Ra = Ac[t + 2];
            unsigned long long Lb = Bc[t], Rb = Bc[t + 2];
            unsigned long long t1 = add2(La, Ra);
            unsigned long long t4 = sub2(Lb, Rb);
            unsigned long long t2 = sub2(La, Ra);
            unsigned long long t3 = add2(Lb, Rb);
            unsigned long long S1 = add2(t1, t4);   // packed (s1r, s1i)
            unsigned long long S2 = add2(t2, t3);   // packed (s2r, s2i)
            float s1r, s1i, s2r, s2i;
            upk2(S1, s1r, s1i);
            upk2(S2, s2r, s2i);
            float er = e[k].x, ei = e[k].y;         // already *0.5
            float nar = er * s1r - ei * s1i;        // a' = e_k * s1
            float nai = er * s1i + ei * s1r;
            float nbr = er * s2r + ei * s2i;        // b' = conj(e_k) * s2
            float nbi = er * s2i - ei * s2r;
            An[t + 1] = pk2(nar, nai);
            Bn[t + 1] = pk2(nbr, nbi);
        }
        __syncthreads();
        unsigned long long* tm;
        tm = Ac; Ac = An; An = tm;
        tm = Bc; Bc = Bn; Bn = tm;
    }

    if (t < NCOEF) {
        // m = 2t+1 -> slot 2t+129 ; m = -(2t+1) -> slot 127-2t
        g_alpha[t] = add2(Ac[2 * t + 129], Ac[127 - 2 * t]);
    }
}

// ---------------- Kernel B: per-element eval ----------------
// S = sum_{j=0}^{63} alpha_j cos((2j+1)theta), split into even/odd-j chains:
// both are 32-term Clenshaw in w = 2cos(4 theta) = u^2 - 2, u = 2cos(2 theta).
//   even chain f_k = cos((4k+1)th): f_0 = c1 = cos th, f_{-1} = c3 = cos 3th
//   odd  chain f_k = cos((4k+3)th): f_0 = c3,          f_{-1} = c1
//   S = c1*(b0e - b1o) + c3*(b0o - b1e)
// (re, im) packed in one f32x2 lane; 2 chains x EPT elements = 8-way ILP.
__global__ void __launch_bounds__(TPB) qsp_eval_kernel(const float* __restrict__ th,
                                                       float* __restrict__ out) {
    __shared__ unsigned long long sc[NCOEF];
    int t = threadIdx.x;
    int base = (blockIdx.x * TPB + t) * EPT;

    // ---- alpha-independent prework (overlaps with coef kernel via PDL) ----
    float4 th4 = *reinterpret_cast<const float4*>(th + base);
    float c1[EPT], c3[EPT];
    unsigned long long W[EPT];
#pragma unroll
    for (int i = 0; i < EPT; i++) {
        float thv = (&th4.x)[i];
        float c = cosf(thv);
        float u = fmaf(4.0f * c, c, -2.0f);       // 2 cos 2th
        float w = fmaf(u, u, -2.0f);              // 2 cos 4th
        c1[i] = c;
        c3[i] = fmaf(u, c, -c);                   // cos 3th
        W[i] = pk2(w, w);
    }

    // ---- wait for coefficient kernel completion ----
    cudaGridDependencySynchronize();

    if (t < NCOEF) sc[t] = g_alpha[t];
    __syncthreads();

    unsigned long long b1e[EPT], b2e[EPT], b1o[EPT], b2o[EPT];
#pragma unroll
    for (int i = 0; i < EPT; i++) {
        b1e[i] = 0ull; b2e[i] = 0ull; b1o[i] = 0ull; b2o[i] = 0ull;
    }

#pragma unroll
    for (int k = NCOEF / 2 - 1; k >= 0; k--) {
        unsigned long long ae = sc[2 * k];
        unsigned long long ao = sc[2 * k + 1];
#pragma unroll
        for (int i = 0; i < EPT; i++) {
            unsigned long long te = sub2(ae, b2e[i]);
            unsigned long long ne = fma2(W[i], b1e[i], te);
            b2e[i] = b1e[i]; b1e[i] = ne;
            unsigned long long to = sub2(ao, b2o[i]);
            unsigned long long no = fma2(W[i], b1o[i], to);
            b2o[i] = b1o[i]; b1o[i] = no;
        }
    }

    float4 re, im;
#pragma unroll
    for (int i = 0; i < EPT; i++) {
        unsigned long long r1 = sub2(b1e[i], b2o[i]);   // b0e - b1o
        unsigned long long r2 = sub2(b1o[i], b2e[i]);   // b0o - b1e
        unsigned long long S = fma2(pk2(c3[i], c3[i]), r2,
                                    mul2(pk2(c1[i], c1[i]), r1));
        float r, q;
        upk2(S, r, q);
        (&re.x)[i] = r;
        (&im.x)[i] = q;
    }

    *reinterpret_cast<float4*>(out + base)           = re;
    *reinterpret_cast<float4*>(out + B_TOTAL + base) = im;
}

// ---------------- Launch ----------------
extern "C" void kernel_launch(void* const* d_in, const int* in_sizes, int n_in,
                              void* d_out, int out_size) {
    const float* th   = (const float*)d_in[0];
    const float* phis = (const float*)d_in[1];
    if (n_in >= 2 && in_sizes[0] == NPHI) {   // defensive input identification
        phis = (const float*)d_in[0];
        th   = (const float*)d_in[1];
    }
    float* out = (float*)d_out;

    qsp_coef_kernel<<<1, 256>>>(phis);

    // Eval kernel with Programmatic Dependent Launch: starts while coef runs,
    // does cosf prework, then grid-syncs on coef completion before reading alpha.
    cudaLaunchConfig_t cfg = {};
    cfg.gridDim  = dim3(B_TOTAL / EPT / TPB);   // 2048
    cfg.blockDim = dim3(TPB);
    cfg.dynamicSmemBytes = 0;
    cfg.stream = 0;
    cudaLaunchAttribute attrs[1];
    attrs[0].id = cudaLaunchAttributeProgrammaticStreamSerialization;
    attrs[0].val.programmaticStreamSerializationAllowed = 1;
    cfg.attrs = attrs;
    cfg.numAttrs = 1;
    cudaLaunchKernelEx(&cfg, qsp_eval_kernel, th, out);
}

// round 4
// speedup vs baseline: 1.8383x; 1.1394x over previous
#include <cuda_runtime.h>

#define B_TOTAL 2097152
#define NPHI    128
#define NSTEP   127
#define NCOEF   64
#define EPT     2
#define TPB     256

// 68 packed (re,im) monomial coefficients:
//  [s*9 + p]       p=0..8 : F_s(v) = sum_p P v^p      (s index 0..3 -> s=1,3,5,7)
//  [36 + s*8 + p]  p=0..7 : G_s(v)
__device__ unsigned long long g_coef[68];

// Chebyshev->monomial tables: MC[q][p] = coeff of v^p in 2*cos(q*phi), v=2cos phi
__device__ __constant__ float MC[9][9] = {
    { 2, 0,  0, 0,  0, 0,  0, 0, 0},
    { 0, 1,  0, 0,  0, 0,  0, 0, 0},
    {-2, 0,  1, 0,  0, 0,  0, 0, 0},
    { 0,-3,  0, 1,  0, 0,  0, 0, 0},
    { 2, 0, -4, 0,  1, 0,  0, 0, 0},
    { 0, 5,  0,-5,  0, 1,  0, 0, 0},
    {-2, 0,  9, 0, -6, 0,  1, 0, 0},
    { 0,-7,  0,14,  0,-7,  0, 1, 0},
    { 2, 0,-16, 0, 20, 0, -8, 0, 1}};
// MU[k][p] = coeff of v^p in U_k: sin((k+1)*phi)/sin(phi), v=2cos phi
__device__ __constant__ float MU[8][8] = {
    { 1, 0, 0, 0,  0, 0, 0, 0},
    { 0, 1, 0, 0,  0, 0, 0, 0},
    {-1, 0, 1, 0,  0, 0, 0, 0},
    { 0,-2, 0, 1,  0, 0, 0, 0},
    { 1, 0,-3, 0,  1, 0, 0, 0},
    { 0, 3, 0,-4,  0, 1, 0, 0},
    {-1, 0, 6, 0, -5, 0, 1, 0},
    { 0,-4, 0,10,  0,-6, 0, 1}};

// ---------------- f32x2 packed helpers ----------------
__device__ __forceinline__ unsigned long long pk2(float lo, float hi) {
    unsigned long long r;
    asm("mov.b64 %0, {%1, %2};" : "=l"(r) : "f"(lo), "f"(hi));
    return r;
}
__device__ __forceinline__ void upk2(unsigned long long v, float& lo, float& hi) {
    asm("mov.b64 {%0, %1}, %2;" : "=f"(lo), "=f"(hi) : "l"(v));
}
__device__ __forceinline__ unsigned long long fma2(unsigned long long a,
                                                   unsigned long long b,
                                                   unsigned long long c) {
    unsigned long long d;
    asm("fma.rn.f32x2 %0, %1, %2, %3;" : "=l"(d) : "l"(a), "l"(b), "l"(c));
    return d;
}
__device__ __forceinline__ unsigned long long mul2(unsigned long long a,
                                                   unsigned long long b) {
    unsigned long long d;
    asm("mul.rn.f32x2 %0, %1, %2;" : "=l"(d) : "l"(a), "l"(b));
    return d;
}
__device__ __forceinline__ unsigned long long add2(unsigned long long a,
                                                   unsigned long long b) {
    unsigned long long d;
    asm("add.rn.f32x2 %0, %1, %2;" : "=l"(d) : "l"(a), "l"(b));
    return d;
}
__device__ __forceinline__ unsigned long long sub2(unsigned long long a,
                                                   unsigned long long b) {
    const unsigned long long NEG1 = 0xBF800000BF800000ull;
    return fma2(NEG1, b, a);
}

// ---------------- Kernel A: coefficient precompute (1 block) ----------------
__global__ void qsp_coef_kernel(const float* __restrict__ phis) {
    cudaTriggerProgrammaticLaunchCompletion();

    __shared__ float2 e[NPHI];                 // (0.5 cos phi, 0.5 sin phi)
    __shared__ unsigned long long A0[257], B0[257], A1[257], B1[257];
    __shared__ float2 al[NCOEF];               // alpha_j for cos((2j+1)theta)
    __shared__ float2 Cc[9][4];                // cos-series coeffs c_{q,s}
    __shared__ float2 Dd[8][4];                // sin-series coeffs d_{q,s} (q=k+1)

    int t = threadIdx.x;
    if (t < NPHI) {
        float s, c;
        sincosf(phis[t], &s, &c);
        e[t] = make_float2(0.5f * c, 0.5f * s);
    }
    for (int i = t; i < 257; i += blockDim.x) {
        A0[i] = 0ull; B0[i] = 0ull; A1[i] = 0ull; B1[i] = 0ull;
    }
    __syncthreads();
    if (t == 0) {
        A0[128] = pk2(2.0f * e[0].x, 2.0f * e[0].y);  // a = e^{i phi_0} at m=0
    }
    __syncthreads();

    unsigned long long *Ac = A0, *Bc = B0, *An = A1, *Bn = B1;
    for (int k = 1; k <= NSTEP; k++) {
        if (t < 255) {
            unsigned long long La = Ac[t], Ra = Ac[t + 2];
            unsigned long long Lb = Bc[t], Rb = Bc[t + 2];
            unsigned long long t1 = add2(La, Ra);
            unsigned long long t4 = sub2(Lb, Rb);
            unsigned long long t2 = sub2(La, Ra);
            unsigned long long t3 = add2(Lb, Rb);
            unsigned long long S1 = add2(t1, t4);
            unsigned long long S2 = add2(t2, t3);
            float s1r, s1i, s2r, s2i;
            upk2(S1, s1r, s1i);
            upk2(S2, s2r, s2i);
            float er = e[k].x, ei = e[k].y;
            float nar = er * s1r - ei * s1i;
            float nai = er * s1i + ei * s1r;
            float nbr = er * s2r + ei * s2i;
            float nbi = er * s2i - ei * s2r;
            An[t + 1] = pk2(nar, nai);
            Bn[t + 1] = pk2(nbr, nbi);
        }
        __syncthreads();
        unsigned long long* tm;
        tm = Ac; Ac = An; An = tm;
        tm = Bc; Bc = Bn; Bn = tm;
    }

    if (t < NCOEF) {
        // symmetrized cosine coefficient: slots m=2t+1 -> 2t+129, m=-(2t+1) -> 127-2t
        unsigned long long s = add2(Ac[2 * t + 129], Ac[127 - 2 * t]);
        float re, im;
        upk2(s, re, im);
        al[t] = make_float2(re, im);
    }
    __syncthreads();

    // Regroup: m = 16q + sigma*s,  s = 2*sidx+1 in {1,3,5,7}
    //   sigma=+1: c += a, d += -a ;  sigma=-1: c += a, d += +a
    if (t < 36) {
        int q = t >> 2, sidx = t & 3;
        float2 aP = make_float2(0.f, 0.f), aM = make_float2(0.f, 0.f);
        if (q <= 7) aP = al[8 * q + sidx];           // m = 16q+s -> j = 8q+sidx
        if (q >= 1) aM = al[8 * q - sidx - 1];       // m = 16q-s -> j = 8q-sidx-1
        Cc[q][sidx] = make_float2(aP.x + aM.x, aP.y + aM.y);
        if (q >= 1) Dd[q - 1][sidx] = make_float2(aM.x - aP.x, aM.y - aP.y);
    }
    __syncthreads();

    // Monomial conversion:
    //   F_s(v) = sum_q c_{q,s} * 0.5 * Ctilde_q(v)  -> P[s][p]
    //   G_s(v) = sum_k d_{k+1,s} * U_k(v)           -> Q[s][p]
    if (t < 36) {
        int p = t >> 2, sidx = t & 3;
        float re = 0.f, im = 0.f;
#pragma unroll
        for (int q = 0; q < 9; q++) {
            float mc = MC[q][p];
            re += Cc[q][sidx].x * mc;
            im += Cc[q][sidx].y * mc;
        }
        g_coef[sidx * 9 + p] = pk2(0.5f * re, 0.5f * im);
    } else if (t >= 64 && t < 96) {
        int tt = t - 64;
        int p = tt >> 2, sidx = tt & 3;
        float re = 0.f, im = 0.f;
#pragma unroll
        for (int k = 0; k < 8; k++) {
            float mu = MU[k][p];
            re += Dd[k][sidx].x * mu;
            im += Dd[k][sidx].y * mu;
        }
        g_coef[36 + sidx * 8 + p] = pk2(re, im);
    }
}

// ---------------- Kernel B: per-element eval ----------------
// S = sum_s cos(s theta) F_s(v) + sin(s theta) sin(16 theta) G_s(v), v = 2cos16theta
__global__ void __launch_bounds__(TPB) qsp_eval_kernel(const float* __restrict__ th,
                                                       float* __restrict__ out) {
    __shared__ unsigned long long sc[68];
    int t = threadIdx.x;
    int base = (blockIdx.x * TPB + t) * EPT;

    // ---- alpha-independent prework (overlaps coef kernel via PDL) ----
    float2 th2 = *reinterpret_cast<const float2*>(th + base);
    unsigned long long VV[EPT];
    float cc[EPT][4], ts[EPT][4];
#pragma unroll
    for (int i = 0; i < EPT; i++) {
        float thv = (&th2.x)[i];
        float sv, cv;
        sincosf(thv, &sv, &cv);
        float u  = fmaf(4.0f * cv, cv, -2.0f);   // 2cos2t
        float w  = fmaf(u, u, -2.0f);            // 2cos4t
        float x8 = fmaf(w, w, -2.0f);            // 2cos8t
        float v  = fmaf(x8, x8, -2.0f);          // 2cos16t
        VV[i] = pk2(v, v);
        // cos(s t), s=1,3,5,7 via step-2theta recurrence
        cc[i][0] = cv;
        cc[i][1] = fmaf(u, cv, -cv);
        cc[i][2] = fmaf(u, cc[i][1], -cc[i][0]);
        cc[i][3] = fmaf(u, cc[i][2], -cc[i][1]);
        // sin(s t)
        float s1 = sv;
        float s3 = fmaf(u, s1, s1);
        float s5 = fmaf(u, s3, -s1);
        float s7 = fmaf(u, s5, -s3);
        // sin 16t
        float sn2  = 2.0f * sv * cv;
        float sn4  = sn2 * u;
        float sn8  = sn4 * w;
        float sn16 = sn8 * x8;
        ts[i][0] = s1 * sn16;
        ts[i][1] = s3 * sn16;
        ts[i][2] = s5 * sn16;
        ts[i][3] = s7 * sn16;
    }

    cudaGridDependencySynchronize();

    if (t < 68) sc[t] = g_coef[t];
    __syncthreads();

    unsigned long long bF[EPT][4], bG[EPT][4];
#pragma unroll
    for (int i = 0; i < EPT; i++)
#pragma unroll
        for (int s = 0; s < 4; s++) {
            bF[i][s] = sc[s * 9 + 8];
            bG[i][s] = sc[36 + s * 8 + 7];
        }

#pragma unroll
    for (int p = 7; p >= 0; p--) {
#pragma unroll
        for (int i = 0; i < EPT; i++)
#pragma unroll
            for (int s = 0; s < 4; s++)
                bF[i][s] = fma2(VV[i], bF[i][s], sc[s * 9 + p]);
    }
#pragma unroll
    for (int p = 6; p >= 0; p--) {
#pragma unroll
        for (int i = 0; i < EPT; i++)
#pragma unroll
            for (int s = 0; s < 4; s++)
                bG[i][s] = fma2(VV[i], bG[i][s], sc[36 + s * 8 + p]);
    }

    float2 re, im;
#pragma unroll
    for (int i = 0; i < EPT; i++) {
        unsigned long long S = mul2(pk2(cc[i][0], cc[i][0]), bF[i][0]);
        S = fma2(pk2(ts[i][0], ts[i][0]), bG[i][0], S);
#pragma unroll
        for (int s = 1; s < 4; s++) {
            S = fma2(pk2(cc[i][s], cc[i][s]), bF[i][s], S);
            S = fma2(pk2(ts[i][s], ts[i][s]), bG[i][s], S);
        }
        float r, q;
        upk2(S, r, q);
        (&re.x)[i] = r;
        (&im.x)[i] = q;
    }

    *reinterpret_cast<float2*>(out + base)           = re;
    *reinterpret_cast<float2*>(out + B_TOTAL + base) = im;
}

// ---------------- Launch ----------------
extern "C" void kernel_launch(void* const* d_in, const int* in_sizes, int n_in,
                              void* d_out, int out_size) {
    const float* th   = (const float*)d_in[0];
    const float* phis = (const float*)d_in[1];
    if (n_in >= 2 && in_sizes[0] == NPHI) {
        phis = (const float*)d_in[0];
        th   = (const float*)d_in[1];
    }
    float* out = (float*)d_out;

    qsp_coef_kernel<<<1, 256>>>(phis);

    cudaLaunchConfig_t cfg = {};
    cfg.gridDim  = dim3(B_TOTAL / EPT / TPB);   // 4096
    cfg.blockDim = dim3(TPB);
    cfg.dynamicSmemBytes = 0;
    cfg.stream = 0;
    cudaLaunchAttribute attrs[1];
    attrs[0].id = cudaLaunchAttributeProgrammaticStreamSerialization;
    attrs[0].val.programmaticStreamSerializationAllowed = 1;
    cfg.attrs = attrs;
    cfg.numAttrs = 1;
    cudaLaunchKernelEx(&cfg, qsp_eval_kernel, th, out);
}

// round 5
// speedup vs baseline: 1.8533x; 1.0082x over previous
#include <cuda_runtime.h>

#define B_TOTAL 2097152
#define NPHI    128
#define NSTEP   127
#define NCOEF   64
#define EPT     4
#define TPB     256

// 68 packed (re,im) monomial coefficients:
//  [s*9 + p]       p=0..8 : F_s(v)   (s index 0..3 -> s=1,3,5,7)
//  [36 + s*8 + p]  p=0..7 : G_s(v)
__device__ unsigned long long g_coef[68];

// Chebyshev->monomial tables: MC[q][p] = coeff of v^p in 2*cos(q*phi), v=2cos phi
__device__ __constant__ float MC[9][9] = {
    { 2, 0,  0, 0,  0, 0,  0, 0, 0},
    { 0, 1,  0, 0,  0, 0,  0, 0, 0},
    {-2, 0,  1, 0,  0, 0,  0, 0, 0},
    { 0,-3,  0, 1,  0, 0,  0, 0, 0},
    { 2, 0, -4, 0,  1, 0,  0, 0, 0},
    { 0, 5,  0,-5,  0, 1,  0, 0, 0},
    {-2, 0,  9, 0, -6, 0,  1, 0, 0},
    { 0,-7,  0,14,  0,-7,  0, 1, 0},
    { 2, 0,-16, 0, 20, 0, -8, 0, 1}};
// MU[k][p] = coeff of v^p in U_k(v) = sin((k+1)phi)/sin(phi)
__device__ __constant__ float MU[8][8] = {
    { 1, 0, 0, 0,  0, 0, 0, 0},
    { 0, 1, 0, 0,  0, 0, 0, 0},
    {-1, 0, 1, 0,  0, 0, 0, 0},
    { 0,-2, 0, 1,  0, 0, 0, 0},
    { 1, 0,-3, 0,  1, 0, 0, 0},
    { 0, 3, 0,-4,  0, 1, 0, 0},
    {-1, 0, 6, 0, -5, 0, 1, 0},
    { 0,-4, 0,10,  0,-6, 0, 1}};

// ---------------- f32x2 packed helpers ----------------
__device__ __forceinline__ unsigned long long pk2(float lo, float hi) {
    unsigned long long r;
    asm("mov.b64 %0, {%1, %2};" : "=l"(r) : "f"(lo), "f"(hi));
    return r;
}
__device__ __forceinline__ void upk2(unsigned long long v, float& lo, float& hi) {
    asm("mov.b64 {%0, %1}, %2;" : "=f"(lo), "=f"(hi) : "l"(v));
}
__device__ __forceinline__ unsigned long long fma2(unsigned long long a,
                                                   unsigned long long b,
                                                   unsigned long long c) {
    unsigned long long d;
    asm("fma.rn.f32x2 %0, %1, %2, %3;" : "=l"(d) : "l"(a), "l"(b), "l"(c));
    return d;
}
__device__ __forceinline__ unsigned long long mul2(unsigned long long a,
                                                   unsigned long long b) {
    unsigned long long d;
    asm("mul.rn.f32x2 %0, %1, %2;" : "=l"(d) : "l"(a), "l"(b));
    return d;
}
__device__ __forceinline__ unsigned long long add2(unsigned long long a,
                                                   unsigned long long b) {
    unsigned long long d;
    asm("add.rn.f32x2 %0, %1, %2;" : "=l"(d) : "l"(a), "l"(b));
    return d;
}
__device__ __forceinline__ unsigned long long sub2(unsigned long long a,
                                                   unsigned long long b) {
    const unsigned long long NEG1 = 0xBF800000BF800000ull;
    return fma2(NEG1, b, a);
}

// ---------------- Kernel A: coefficient precompute (1 block) ----------------
__global__ void qsp_coef_kernel(const float* __restrict__ phis) {
    cudaTriggerProgrammaticLaunchCompletion();

    __shared__ float2 e[NPHI];                 // (0.5 cos phi, 0.5 sin phi)
    __shared__ unsigned long long A0[257], B0[257], A1[257], B1[257];
    __shared__ float2 al[NCOEF];
    __shared__ float2 Cc[9][4];
    __shared__ float2 Dd[8][4];

    int t = threadIdx.x;
    if (t < NPHI) {
        float s, c;
        sincosf(phis[t], &s, &c);
        e[t] = make_float2(0.5f * c, 0.5f * s);
    }
    for (int i = t; i < 257; i += blockDim.x) {
        A0[i] = 0ull; B0[i] = 0ull; A1[i] = 0ull; B1[i] = 0ull;
    }
    __syncthreads();
    if (t == 0) {
        A0[128] = pk2(2.0f * e[0].x, 2.0f * e[0].y);  // a = e^{i phi_0} at m=0
    }
    __syncthreads();

    unsigned long long *Ac = A0, *Bc = B0, *An = A1, *Bn = B1;
    for (int k = 1; k <= NSTEP; k++) {
        // Active-range gating: after step k, nonzero slots are 128-k .. 128+k.
        // Output slot t+1 must lie in that range -> t in [127-k, 127+k].
        if (t < 255 && (unsigned)(t - (127 - k)) <= (unsigned)(2 * k)) {
            unsigned long long La = Ac[t], Ra = Ac[t + 2];
            unsigned long long Lb = Bc[t], Rb = Bc[t + 2];
            unsigned long long t1 = add2(La, Ra);
            unsigned long long t4 = sub2(Lb, Rb);
            unsigned long long t2 = sub2(La, Ra);
            unsigned long long t3 = add2(Lb, Rb);
            unsigned long long S1 = add2(t1, t4);
            unsigned long long S2 = add2(t2, t3);
            float s1r, s1i, s2r, s2i;
            upk2(S1, s1r, s1i);
            upk2(S2, s2r, s2i);
            float er = e[k].x, ei = e[k].y;
            float nar = er * s1r - ei * s1i;
            float nai = er * s1i + ei * s1r;
            float nbr = er * s2r + ei * s2i;
            float nbi = er * s2i - ei * s2r;
            An[t + 1] = pk2(nar, nai);
            Bn[t + 1] = pk2(nbr, nbi);
        }
        __syncthreads();
        unsigned long long* tm;
        tm = Ac; Ac = An; An = tm;
        tm = Bc; Bc = Bn; Bn = tm;
    }

    if (t < NCOEF) {
        unsigned long long s = add2(Ac[2 * t + 129], Ac[127 - 2 * t]);
        float re, im;
        upk2(s, re, im);
        al[t] = make_float2(re, im);
    }
    __syncthreads();

    // Regroup: m = 16q +/- s,  s = 2*sidx+1 in {1,3,5,7}
    if (t < 36) {
        int q = t >> 2, sidx = t & 3;
        float2 aP = make_float2(0.f, 0.f), aM = make_float2(0.f, 0.f);
        if (q <= 7) aP = al[8 * q + sidx];
        if (q >= 1) aM = al[8 * q - sidx - 1];
        Cc[q][sidx] = make_float2(aP.x + aM.x, aP.y + aM.y);
        if (q >= 1) Dd[q - 1][sidx] = make_float2(aM.x - aP.x, aM.y - aP.y);
    }
    __syncthreads();

    if (t < 36) {
        int p = t >> 2, sidx = t & 3;
        float re = 0.f, im = 0.f;
#pragma unroll
        for (int q = 0; q < 9; q++) {
            float mc = MC[q][p];
            re += Cc[q][sidx].x * mc;
            im += Cc[q][sidx].y * mc;
        }
        g_coef[sidx * 9 + p] = pk2(0.5f * re, 0.5f * im);
    } else if (t >= 64 && t < 96) {
        int tt = t - 64;
        int p = tt >> 2, sidx = tt & 3;
        float re = 0.f, im = 0.f;
#pragma unroll
        for (int k = 0; k < 8; k++) {
            float mu = MU[k][p];
            re += Dd[k][sidx].x * mu;
            im += Dd[k][sidx].y * mu;
        }
        g_coef[36 + sidx * 8 + p] = pk2(re, im);
    }
}

// ---------------- Kernel B: per-element eval (EPT=4, phased F then G) ------
// S = sum_s cos(s th) F_s(v) + sin(s th) sin(16 th) G_s(v),  v = 2cos(16 th)
__global__ void __launch_bounds__(TPB) qsp_eval_kernel(const float* __restrict__ th,
                                                       float* __restrict__ out) {
    __shared__ unsigned long long sc[68];
    int t = threadIdx.x;
    int base = (blockIdx.x * TPB + t) * EPT;

    // ---- alpha-independent prework (overlaps coef kernel via PDL) ----
    float4 th4 = *reinterpret_cast<const float4*>(th + base);
    unsigned long long VV[EPT];
    float cc[EPT][4], ts[EPT][4];
#pragma unroll
    for (int i = 0; i < EPT; i++) {
        float thv = (&th4.x)[i];
        float sv, cv;
        sincosf(thv, &sv, &cv);
        float u  = fmaf(4.0f * cv, cv, -2.0f);   // 2cos2t
        float w  = fmaf(u, u, -2.0f);            // 2cos4t
        float x8 = fmaf(w, w, -2.0f);            // 2cos8t
        float v  = fmaf(x8, x8, -2.0f);          // 2cos16t
        VV[i] = pk2(v, v);
        cc[i][0] = cv;
        cc[i][1] = fmaf(u, cv, -cv);             // cos3t
        cc[i][2] = fmaf(u, cc[i][1], -cc[i][0]); // cos5t
        cc[i][3] = fmaf(u, cc[i][2], -cc[i][1]); // cos7t
        float s1 = sv;
        float s3 = fmaf(u, s1, s1);
        float s5 = fmaf(u, s3, -s1);
        float s7 = fmaf(u, s5, -s3);
        float sn2  = 2.0f * sv * cv;
        float sn4  = sn2 * u;
        float sn8  = sn4 * w;
        float sn16 = sn8 * x8;
        ts[i][0] = s1 * sn16;
        ts[i][1] = s3 * sn16;
        ts[i][2] = s5 * sn16;
        ts[i][3] = s7 * sn16;
    }

    cudaGridDependencySynchronize();
    if (t < 68) sc[t] = g_coef[t];
    __syncthreads();

    unsigned long long b[EPT][4];
    unsigned long long S[EPT];

    // ---- F phase ----
#pragma unroll
    for (int i = 0; i < EPT; i++)
#pragma unroll
        for (int s = 0; s < 4; s++)
            b[i][s] = sc[s * 9 + 8];
#pragma unroll
    for (int p = 7; p >= 0; p--) {
#pragma unroll
        for (int i = 0; i < EPT; i++)
#pragma unroll
            for (int s = 0; s < 4; s++)
                b[i][s] = fma2(VV[i], b[i][s], sc[s * 9 + p]);
    }
#pragma unroll
    for (int i = 0; i < EPT; i++) {
        S[i] = mul2(pk2(cc[i][0], cc[i][0]), b[i][0]);
#pragma unroll
        for (int s = 1; s < 4; s++)
            S[i] = fma2(pk2(cc[i][s], cc[i][s]), b[i][s], S[i]);
    }

    // ---- G phase (reuses b registers) ----
#pragma unroll
    for (int i = 0; i < EPT; i++)
#pragma unroll
        for (int s = 0; s < 4; s++)
            b[i][s] = sc[36 + s * 8 + 7];
#pragma unroll
    for (int p = 6; p >= 0; p--) {
#pragma unroll
        for (int i = 0; i < EPT; i++)
#pragma unroll
            for (int s = 0; s < 4; s++)
                b[i][s] = fma2(VV[i], b[i][s], sc[36 + s * 8 + p]);
    }

    float4 re, im;
#pragma unroll
    for (int i = 0; i < EPT; i++) {
#pragma unroll
        for (int s = 0; s < 4; s++)
            S[i] = fma2(pk2(ts[i][s], ts[i][s]), b[i][s], S[i]);
        float r, q;
        upk2(S[i], r, q);
        (&re.x)[i] = r;
        (&im.x)[i] = q;
    }

    *reinterpret_cast<float4*>(out + base)           = re;
    *reinterpret_cast<float4*>(out + B_TOTAL + base) = im;
}

// ---------------- Launch ----------------
extern "C" void kernel_launch(void* const* d_in, const int* in_sizes, int n_in,
                              void* d_out, int out_size) {
    const float* th   = (const float*)d_in[0];
    const float* phis = (const float*)d_in[1];
    if (n_in >= 2 && in_sizes[0] == NPHI) {
        phis = (const float*)d_in[0];
        th   = (const float*)d_in[1];
    }
    float* out = (float*)d_out;

    qsp_coef_kernel<<<1, 256>>>(phis);

    cudaLaunchConfig_t cfg = {};
    cfg.gridDim  = dim3(B_TOTAL / EPT / TPB);   // 2048
    cfg.blockDim = dim3(TPB);
    cfg.dynamicSmemBytes = 0;
    cfg.stream = 0;
    cudaLaunchAttribute attrs[1];
    attrs[0].id = cudaLaunchAttributeProgrammaticStreamSerialization;
    attrs[0].val.programmaticStreamSerializationAllowed = 1;
    cfg.attrs = attrs;
    cfg.numAttrs = 1;
    cudaLaunchKernelEx(&cfg, qsp_eval_kernel, th, out);
}

// round 6
// speedup vs baseline: 1.8725x; 1.0104x over previous
#include <cuda_runtime.h>

#define B_TOTAL 2097152
#define NPHI    128
#define NSTEP   127
#define NCOEF   64
#define EPT     4
#define TPB     256

// 68 packed (re,im) monomial coefficients:
//  [s*9 + p]       p=0..8 : F_s(v)   (s index 0..3 -> s=1,3,5,7)
//  [36 + s*8 + p]  p=0..7 : G_s(v)
__device__ unsigned long long g_coef[68];

// Chebyshev->monomial tables: MC[q][p] = coeff of v^p in 2*cos(q*phi), v=2cos phi
__device__ __constant__ float MC[9][9] = {
    { 2, 0,  0, 0,  0, 0,  0, 0, 0},
    { 0, 1,  0, 0,  0, 0,  0, 0, 0},
    {-2, 0,  1, 0,  0, 0,  0, 0, 0},
    { 0,-3,  0, 1,  0, 0,  0, 0, 0},
    { 2, 0, -4, 0,  1, 0,  0, 0, 0},
    { 0, 5,  0,-5,  0, 1,  0, 0, 0},
    {-2, 0,  9, 0, -6, 0,  1, 0, 0},
    { 0,-7,  0,14,  0,-7,  0, 1, 0},
    { 2, 0,-16, 0, 20, 0, -8, 0, 1}};
// MU[k][p] = coeff of v^p in U_k(v) = sin((k+1)phi)/sin(phi)
__device__ __constant__ float MU[8][8] = {
    { 1, 0, 0, 0,  0, 0, 0, 0},
    { 0, 1, 0, 0,  0, 0, 0, 0},
    {-1, 0, 1, 0,  0, 0, 0, 0},
    { 0,-2, 0, 1,  0, 0, 0, 0},
    { 1, 0,-3, 0,  1, 0, 0, 0},
    { 0, 3, 0,-4,  0, 1, 0, 0},
    {-1, 0, 6, 0, -5, 0, 1, 0},
    { 0,-4, 0,10,  0,-6, 0, 1}};

// ---------------- f32x2 packed helpers ----------------
__device__ __forceinline__ unsigned long long pk2(float lo, float hi) {
    unsigned long long r;
    asm("mov.b64 %0, {%1, %2};" : "=l"(r) : "f"(lo), "f"(hi));
    return r;
}
__device__ __forceinline__ void upk2(unsigned long long v, float& lo, float& hi) {
    asm("mov.b64 {%0, %1}, %2;" : "=f"(lo), "=f"(hi) : "l"(v));
}
__device__ __forceinline__ unsigned long long fma2(unsigned long long a,
                                                   unsigned long long b,
                                                   unsigned long long c) {
    unsigned long long d;
    asm("fma.rn.f32x2 %0, %1, %2, %3;" : "=l"(d) : "l"(a), "l"(b), "l"(c));
    return d;
}
__device__ __forceinline__ unsigned long long mul2(unsigned long long a,
                                                   unsigned long long b) {
    unsigned long long d;
    asm("mul.rn.f32x2 %0, %1, %2;" : "=l"(d) : "l"(a), "l"(b));
    return d;
}
__device__ __forceinline__ unsigned long long add2(unsigned long long a,
                                                   unsigned long long b) {
    unsigned long long d;
    asm("add.rn.f32x2 %0, %1, %2;" : "=l"(d) : "l"(a), "l"(b));
    return d;
}
__device__ __forceinline__ unsigned long long sub2(unsigned long long a,
                                                   unsigned long long b) {
    const unsigned long long NEG1 = 0xBF800000BF800000ull;
    return fma2(NEG1, b, a);
}

// One W*Rz stencil application on packed (re,im) values.
//   s1 = (La+Ra) + (Lb-Rb); s2 = (La-Ra) + (Lb+Rb)
//   a' = e*s1 ; b' = conj(e)*s2     (e carries the 0.5 fold)
__device__ __forceinline__ void stencil(float er, float ei,
                                        unsigned long long La, unsigned long long Ra,
                                        unsigned long long Lb, unsigned long long Rb,
                                        unsigned long long& ao, unsigned long long& bo) {
    unsigned long long S1 = add2(add2(La, Ra), sub2(Lb, Rb));
    unsigned long long S2 = add2(sub2(La, Ra), add2(Lb, Rb));
    float s1r, s1i, s2r, s2i;
    upk2(S1, s1r, s1i);
    upk2(S2, s2r, s2i);
    float nar = er * s1r - ei * s1i;
    float nai = er * s1i + ei * s1r;
    float nbr = er * s2r + ei * s2i;
    float nbi = er * s2i - ei * s2r;
    ao = pk2(nar, nai);
    bo = pk2(nbr, nbi);
}

// ---------------- Kernel A: coefficient precompute (1 block) ----------------
// 2-step fused stencil: 63 fused pairs + 1 single step = 64 barriers.
// Slot layout: slot = m + 129, data slots 2..256, permanent zeros at 0,1,257,258.
#define NSLOT 259
__global__ void qsp_coef_kernel(const float* __restrict__ phis) {
    cudaTriggerProgrammaticLaunchCompletion();

    __shared__ float2 e[NPHI];                 // (0.5 cos phi, 0.5 sin phi)
    __shared__ unsigned long long A0[NSLOT], B0[NSLOT], A1[NSLOT], B1[NSLOT];
    __shared__ float2 al[NCOEF];
    __shared__ float2 Cc[9][4];
    __shared__ float2 Dd[8][4];

    int t = threadIdx.x;
    if (t < NPHI) {
        float s, c;
        sincosf(phis[t], &s, &c);
        e[t] = make_float2(0.5f * c, 0.5f * s);
    }
    for (int i = t; i < NSLOT; i += blockDim.x) {
        A0[i] = 0ull; B0[i] = 0ull; A1[i] = 0ull; B1[i] = 0ull;
    }
    __syncthreads();
    if (t == 0) {
        A0[129] = pk2(2.0f * e[0].x, 2.0f * e[0].y);  // a = e^{i phi_0} at m=0
    }
    __syncthreads();

    unsigned long long *Ac = A0, *Bc = B0, *An = A1, *Bn = B1;

    // Fused pairs: steps (k, k+1), k = 1,3,...,125
    for (int k = 1; k + 1 <= NSTEP - 1; k += 2) {
        // After the pair, active writes are slots [128-k, 130+k] -> t in [126-k, 128+k]
        if (t < 255 && (unsigned)(t - (126 - k)) <= (unsigned)(2 * k + 2)) {
            unsigned long long a0 = Ac[t],     a1 = Ac[t + 2], a2 = Ac[t + 4];
            unsigned long long b0 = Bc[t],     b1 = Bc[t + 2], b2 = Bc[t + 4];
            float er = e[k].x,     ei = e[k].y;
            float fr = e[k + 1].x, fi = e[k + 1].y;
            unsigned long long iaL, ibL, iaR, ibR, fa, fb;
            stencil(er, ei, a0, a1, b0, b1, iaL, ibL);   // intermediate at m-1
            stencil(er, ei, a1, a2, b1, b2, iaR, ibR);   // intermediate at m+1
            stencil(fr, fi, iaL, iaR, ibL, ibR, fa, fb); // final at m
            An[t + 2] = fa;
            Bn[t + 2] = fb;
        }
        __syncthreads();
        unsigned long long* tm;
        tm = Ac; Ac = An; An = tm;
        tm = Bc; Bc = Bn; Bn = tm;
    }

    // Final single step k = 127
    if (t < 255) {
        unsigned long long La = Ac[t + 1], Ra = Ac[t + 3];
        unsigned long long Lb = Bc[t + 1], Rb = Bc[t + 3];
        unsigned long long fa, fb;
        stencil(e[NSTEP].x, e[NSTEP].y, La, Ra, Lb, Rb, fa, fb);
        An[t + 2] = fa;
        Bn[t + 2] = fb;
    }
    __syncthreads();
    {
        unsigned long long* tm;
        tm = Ac; Ac = An; An = tm;
        tm = Bc; Bc = Bn; Bn = tm;
    }

    if (t < NCOEF) {
        // m = 2t+1 -> slot 2t+130 ; m = -(2t+1) -> slot 128-2t
        unsigned long long s = add2(Ac[2 * t + 130], Ac[128 - 2 * t]);
        float re, im;
        upk2(s, re, im);
        al[t] = make_float2(re, im);
    }
    __syncthreads();

    // Regroup: m = 16q +/- s,  s = 2*sidx+1 in {1,3,5,7}
    if (t < 36) {
        int q = t >> 2, sidx = t & 3;
        float2 aP = make_float2(0.f, 0.f), aM = make_float2(0.f, 0.f);
        if (q <= 7) aP = al[8 * q + sidx];
        if (q >= 1) aM = al[8 * q - sidx - 1];
        Cc[q][sidx] = make_float2(aP.x + aM.x, aP.y + aM.y);
        if (q >= 1) Dd[q - 1][sidx] = make_float2(aM.x - aP.x, aM.y - aP.y);
    }
    __syncthreads();

    if (t < 36) {
        int p = t >> 2, sidx = t & 3;
        float re = 0.f, im = 0.f;
#pragma unroll
        for (int q = 0; q < 9; q++) {
            float mc = MC[q][p];
            re += Cc[q][sidx].x * mc;
            im += Cc[q][sidx].y * mc;
        }
        g_coef[sidx * 9 + p] = pk2(0.5f * re, 0.5f * im);
    } else if (t >= 64 && t < 96) {
        int tt = t - 64;
        int p = tt >> 2, sidx = tt & 3;
        float re = 0.f, im = 0.f;
#pragma unroll
        for (int k = 0; k < 8; k++) {
            float mu = MU[k][p];
            re += Dd[k][sidx].x * mu;
            im += Dd[k][sidx].y * mu;
        }
        g_coef[36 + sidx * 8 + p] = pk2(re, im);
    }
}

// ---------------- Kernel B: per-element eval (EPT=4, phased F then G) ------
// S = sum_s cos(s th) F_s(v) + sin(s th) sin(16 th) G_s(v),  v = 2cos(16 th)
__global__ void __launch_bounds__(TPB, 4) qsp_eval_kernel(const float* __restrict__ th,
                                                          float* __restrict__ out) {
    __shared__ unsigned long long sc[68];
    int t = threadIdx.x;
    int base = (blockIdx.x * TPB + t) * EPT;

    // ---- alpha-independent prework (overlaps coef kernel via PDL) ----
    float4 th4 = *reinterpret_cast<const float4*>(th + base);
    unsigned long long VV[EPT];
    float cc[EPT][4], ts[EPT][4];
#pragma unroll
    for (int i = 0; i < EPT; i++) {
        float thv = (&th4.x)[i];
        float sv = __sinf(thv);                  // MUFU fast path
        float cv = __cosf(thv);
        float u  = fmaf(4.0f * cv, cv, -2.0f);   // 2cos2t
        float w  = fmaf(u, u, -2.0f);            // 2cos4t
        float x8 = fmaf(w, w, -2.0f);            // 2cos8t
        float v  = fmaf(x8, x8, -2.0f);          // 2cos16t
        VV[i] = pk2(v, v);
        cc[i][0] = cv;
        cc[i][1] = fmaf(u, cv, -cv);             // cos3t
        cc[i][2] = fmaf(u, cc[i][1], -cc[i][0]); // cos5t
        cc[i][3] = fmaf(u, cc[i][2], -cc[i][1]); // cos7t
        float s1 = sv;
        float s3 = fmaf(u, s1, s1);
        float s5 = fmaf(u, s3, -s1);
        float s7 = fmaf(u, s5, -s3);
        float sn2  = 2.0f * sv * cv;
        float sn4  = sn2 * u;
        float sn8  = sn4 * w;
        float sn16 = sn8 * x8;
        ts[i][0] = s1 * sn16;
        ts[i][1] = s3 * sn16;
        ts[i][2] = s5 * sn16;
        ts[i][3] = s7 * sn16;
    }

    cudaGridDependencySynchronize();
    if (t < 68) sc[t] = g_coef[t];
    __syncthreads();

    unsigned long long b[EPT][4];
    unsigned long long S[EPT];

    // ---- F phase ----
#pragma unroll
    for (int i = 0; i < EPT; i++)
#pragma unroll
        for (int s = 0; s < 4; s++)
            b[i][s] = sc[s * 9 + 8];
#pragma unroll
    for (int p = 7; p >= 0; p--) {
#pragma unroll
        for (int i = 0; i < EPT; i++)
#pragma unroll
            for (int s = 0; s < 4; s++)
                b[i][s] = fma2(VV[i], b[i][s], sc[s * 9 + p]);
    }
#pragma unroll
    for (int i = 0; i < EPT; i++) {
        S[i] = mul2(pk2(cc[i][0], cc[i][0]), b[i][0]);
#pragma unroll
        for (int s = 1; s < 4; s++)
            S[i] = fma2(pk2(cc[i][s], cc[i][s]), b[i][s], S[i]);
    }

    // ---- G phase (reuses b registers) ----
#pragma unroll
    for (int i = 0; i < EPT; i++)
#pragma unroll
        for (int s = 0; s < 4; s++)
            b[i][s] = sc[36 + s * 8 + 7];
#pragma unroll
    for (int p = 6; p >= 0; p--) {
#pragma unroll
        for (int i = 0; i < EPT; i++)
#pragma unroll
            for (int s = 0; s < 4; s++)
                b[i][s] = fma2(VV[i], b[i][s], sc[36 + s * 8 + p]);
    }

    float4 re, im;
#pragma unroll
    for (int i = 0; i < EPT; i++) {
#pragma unroll
        for (int s = 0; s < 4; s++)
            S[i] = fma2(pk2(ts[i][s], ts[i][s]), b[i][s], S[i]);
        float r, q;
        upk2(S[i], r, q);
        (&re.x)[i] = r;
        (&im.x)[i] = q;
    }

    *reinterpret_cast<float4*>(out + base)           = re;
    *reinterpret_cast<float4*>(out + B_TOTAL + base) = im;
}

// ---------------- Launch ----------------
extern "C" void kernel_launch(void* const* d_in, const int* in_sizes, int n_in,
                              void* d_out, int out_size) {
    const float* th   = (const float*)d_in[0];
    const float* phis = (const float*)d_in[1];
    if (n_in >= 2 && in_sizes[0] == NPHI) {
        phis = (const float*)d_in[0];
        th   = (const float*)d_in[1];
    }
    float* out = (float*)d_out;

    qsp_coef_kernel<<<1, 256>>>(phis);

    cudaLaunchConfig_t cfg = {};
    cfg.gridDim  = dim3(B_TOTAL / EPT / TPB);   // 2048
    cfg.blockDim = dim3(TPB);
    cfg.dynamicSmemBytes = 0;
    cfg.stream = 0;
    cudaLaunchAttribute attrs[1];
    attrs[0].id = cudaLaunchAttributeProgrammaticStreamSerialization;
    attrs[0].val.programmaticStreamSerializationAllowed = 1;
    cfg.attrs = attrs;
    cfg.numAttrs = 1;
    cudaLaunchKernelEx(&cfg, qsp_eval_kernel, th, out);
}